// round 16
// baseline (speedup 1.0000x reference)
#include <cuda_runtime.h>
#include <cuda_bf16.h>
#include <cstdint>

#define N_NODES_MAX 50000
#define N_EDGES_MAX 800000
#define NFEAT 128
#define HID 256
#define BN_EPS 1e-5f

typedef __nv_bfloat16 bf16;

// ---------------- scratch (static __device__, no allocation) ----------------
__device__ float  g_h  [(size_t)N_NODES_MAX * HID];
__device__ bf16   g_ahi[(size_t)N_NODES_MAX * HID];
__device__ bf16   g_alo[(size_t)N_NODES_MAX * HID];
__device__ bf16   g_w1h[HID * NFEAT], g_w1l[HID * NFEAT];     // [N][K] transposed
__device__ bf16   g_w2h[HID * HID],   g_w2l[HID * HID];
__device__ bf16   g_wfh[HID * HID],   g_wfl[HID * HID];
__device__ float  g_dis[N_NODES_MAX];
__device__ int    g_deg[N_NODES_MAX];
__device__ int    g_rowoff[N_NODES_MAX];
__device__ int    g_cursor[N_NODES_MAX];
__device__ int    g_src[N_EDGES_MAX];
__device__ int    g_dst[N_EDGES_MAX];
__device__ int    g_csr[N_EDGES_MAX];
__device__ int    g_part[256];
__device__ int    g_is32;        // statically 0; set-only (monotone)
__device__ double g_sum[HID];
__device__ double g_sumsq[HID];
__device__ float  g_bns[HID];
__device__ float  g_bnt[HID];
__device__ float  g_bias2[HID];  // folded FC bias

// ---------------- prep: init + dtype probe fused ----------------
__global__ void init_kernel(const unsigned long long* __restrict__ p,
                            int Escan, int n, int M) {
    int i = blockIdx.x * blockDim.x + threadIdx.x;
    if (i < n) g_deg[i] = 0;
    if (i < HID) {
        g_sum[i] = 0.0; g_sumsq[i] = 0.0;
        g_bias2[i] = 0.f;
    }
    bool bad = (i < Escan) && (p[i] >= (unsigned long long)M);
    unsigned b = __ballot_sync(~0u, bad);
    if (b && (threadIdx.x & 31) == 0) g_is32 = 1;
}

__global__ void convert_kernel(const void* __restrict__ ei, int E) {
    int e = blockIdx.x * blockDim.x + threadIdx.x;
    if (e >= E) return;
    int s, d;
    if (g_is32) {
        const int* p = (const int*)ei;
        s = p[e]; d = p[E + e];
    } else {
        const long long* p = (const long long*)ei;
        s = (int)p[e]; d = (int)p[(size_t)E + e];
    }
    g_src[e] = s;
    g_dst[e] = d;
    atomicAdd(&g_deg[d], 1);
}

__global__ void __launch_bounds__(256)
partsum_kernel(int M) {
    __shared__ int sh[8];
    const int tid = threadIdx.x;
    int i = blockIdx.x * 256 + tid;
    int v = (i < M) ? g_deg[i] : 0;
    #pragma unroll
    for (int o = 16; o > 0; o >>= 1) v += __shfl_down_sync(~0u, v, o);
    if ((tid & 31) == 0) sh[tid >> 5] = v;
    __syncthreads();
    if (tid < 8) {
        int w = sh[tid];
        #pragma unroll
        for (int o = 4; o > 0; o >>= 1) w += __shfl_down_sync(0xffu, w, o);
        if (tid == 0) g_part[blockIdx.x] = w;
    }
}

// scanfinal: block offset computed inline; replaces separate scanpart kernel.
__global__ void __launch_bounds__(256)
scanfinal_kernel(int M, int NB) {
    __shared__ int sh[8];
    __shared__ int shOff;
    const int tid = threadIdx.x;

    int pv = (tid < NB && tid < blockIdx.x) ? g_part[tid] : 0;
    #pragma unroll
    for (int o = 16; o > 0; o >>= 1) pv += __shfl_down_sync(~0u, pv, o);
    if ((tid & 31) == 0) sh[tid >> 5] = pv;
    __syncthreads();
    if (tid < 8) {
        int w = sh[tid];
        #pragma unroll
        for (int o = 4; o > 0; o >>= 1) w += __shfl_down_sync(0xffu, w, o);
        if (tid == 0) shOff = w;
    }
    __syncthreads();
    const int blockOff = shOff;
    __syncthreads();

    int i = blockIdx.x * 256 + tid;
    int d = (i < M) ? g_deg[i] : 0;
    int v = d;
    #pragma unroll
    for (int o = 1; o < 32; o <<= 1) {
        int u = __shfl_up_sync(~0u, v, o);
        if ((tid & 31) >= o) v += u;
    }
    if ((tid & 31) == 31) sh[tid >> 5] = v;
    __syncthreads();
    if (tid < 8) {
        int w = sh[tid];
        #pragma unroll
        for (int o = 1; o < 8; o <<= 1) {
            int u = __shfl_up_sync(0xffu, w, o);
            if (tid >= o) w += u;
        }
        sh[tid] = w;
    }
    __syncthreads();
    int warpBase = (tid >= 32) ? sh[(tid >> 5) - 1] : 0;
    int excl = blockOff + warpBase + v - d;
    if (i < M) {
        g_rowoff[i] = excl;
        g_cursor[i] = excl;
        g_dis[i] = rsqrtf((float)(d + 1));
    }
}

__global__ void fill_kernel(int E) {
    int e = blockIdx.x * blockDim.x + threadIdx.x;
    if (e >= E) return;
    int d = g_dst[e];
    int pos = atomicAdd(&g_cursor[d], 1);
    g_csr[pos] = g_src[e];
}

// ---------------- W1 + W2 splits (transposed) ----------------
__global__ void wsplit_all(const float* __restrict__ W1,
                           const float* __restrict__ W2) {
    int idx = blockIdx.x * blockDim.x + threadIdx.x;
    const float* W; bf16 *hip, *lop; int K; int off;
    const int S1 = NFEAT * HID, S2 = S1 + HID * HID;
    if (idx < S1)      { W = W1; hip = g_w1h; lop = g_w1l; K = NFEAT; off = idx; }
    else if (idx < S2) { W = W2; hip = g_w2h; lop = g_w2l; K = HID;   off = idx - S1; }
    else return;
    int k = off >> 8;
    int n = off & 255;
    float v = W[off];
    bf16 h = __float2bfloat16(v);
    bf16 l = __float2bfloat16(v - __bfloat162float(h));
    hip[(size_t)n * K + k] = h;
    lop[(size_t)n * K + k] = l;
}

// ---------------- Wfc fold (reads precomputed g_bns/g_bnt from bn2) -------
__global__ void __launch_bounds__(HID)
wfc_fold_kernel(const float* __restrict__ Wfc,
                const float* __restrict__ bfc) {
    int k = blockIdx.x;
    int n = threadIdx.x;
    float sc = g_bns[k];
    float tt = g_bnt[k];
    float w = Wfc[(size_t)k * HID + n];
    float v = sc * w;
    bf16 h = __float2bfloat16(v);
    bf16 l = __float2bfloat16(v - __bfloat162float(h));
    g_wfh[(size_t)n * HID + k] = h;
    g_wfl[(size_t)n * HID + k] = l;
    float contrib = tt * w;
    if (k == 0) contrib += bfc[n];   // add base bias exactly once
    atomicAdd(&g_bias2[n], contrib);
}

// ---------------- split helpers ----------------
__device__ __forceinline__ uint32_t pack2(float a, float b) {
    __nv_bfloat162 t = __floats2bfloat162_rn(a, b);
    return *(uint32_t*)&t;
}

__device__ __forceinline__ void split4(const float4 v, uint2& H, uint2& L) {
    float hx = __bfloat162float(__float2bfloat16(v.x));
    float hy = __bfloat162float(__float2bfloat16(v.y));
    float hz = __bfloat162float(__float2bfloat16(v.z));
    float hw = __bfloat162float(__float2bfloat16(v.w));
    H.x = pack2(v.x, v.y); H.y = pack2(v.z, v.w);
    L.x = pack2(v.x - hx, v.y - hy); L.y = pack2(v.z - hz, v.w - hw);
}

// ---------------- tensor-core GEMM ----------------
__device__ __forceinline__ void mma16816(float* c, const uint32_t* a,
                                         const uint32_t* b) {
    asm volatile(
        "mma.sync.aligned.m16n8k16.row.col.f32.bf16.bf16.f32 "
        "{%0,%1,%2,%3}, {%4,%5,%6,%7}, {%8,%9}, {%0,%1,%2,%3};"
        : "+f"(c[0]), "+f"(c[1]), "+f"(c[2]), "+f"(c[3])
        : "r"(a[0]), "r"(a[1]), "r"(a[2]), "r"(a[3]), "r"(b[0]), "r"(b[1]));
}

__device__ __forceinline__ void cpa16(void* s, const void* g) {
    uint32_t sa = (uint32_t)__cvta_generic_to_shared(s);
    asm volatile("cp.async.cg.shared.global [%0], [%1], 16;" :: "r"(sa), "l"(g));
}

#define SM_STAGE 36864
#define SM_AL    6144
#define SM_BH    12288
#define SM_BL    24576

template<int K, bool ADD_BIAS, bool STATS, bool OUT_SPLIT>
__global__ void __launch_bounds__(256)
gemm_mma(const bf16* __restrict__ Ahi, const bf16* __restrict__ Alo,
         const bf16* __restrict__ Bhi, const bf16* __restrict__ Blo,
         float* __restrict__ C, bf16* __restrict__ Ohi, bf16* __restrict__ Olo,
         int M, const float* __restrict__ bias)
{
    extern __shared__ char smbuf[];
    __shared__ float s_sum[HID], s_sq[HID];
    constexpr int NK = K / 16;
    const int tid = threadIdx.x;
    const int l   = tid & 31;
    const int wid = tid >> 5;
    const int wm  = (wid & 1) * 64;
    const int wn  = (wid >> 1) * 64;
    const int rowBase = blockIdx.x * 128;

    const int arow  = tid >> 1;
    const int ahalf = tid & 1;
    const int gar   = min(rowBase + arow, M - 1);
    const size_t aoff = (size_t)gar * K + ahalf * 8;
    const int asm_off = arow * 48 + ahalf * 16;

    if (STATS) { s_sum[tid] = 0.f; s_sq[tid] = 0.f; }

    float acc[4][8][4] = {};

    auto issue = [&](int kt, int buf) {
        char* st = smbuf + buf * SM_STAGE;
        int ko = kt * 16;
        cpa16(st + asm_off,         Ahi + aoff + ko);
        cpa16(st + SM_AL + asm_off, Alo + aoff + ko);
        #pragma unroll
        for (int q = 0; q < 2; q++) {
            int slot = tid + q * 256;
            int n = slot >> 1, hh = slot & 1;
            size_t boff = (size_t)n * K + ko + hh * 8;
            int so = n * 48 + hh * 16;
            cpa16(st + SM_BH + so, Bhi + boff);
            cpa16(st + SM_BL + so, Blo + boff);
        }
    };

    issue(0, 0);
    asm volatile("cp.async.commit_group;");

    const int kq = l & 3;
    const int rl = l >> 2;

    for (int kt = 0; kt < NK; kt++) {
        const int buf = kt & 1;
        if (kt + 1 < NK) {
            issue(kt + 1, buf ^ 1);
            asm volatile("cp.async.commit_group;");
            asm volatile("cp.async.wait_group 1;");
        } else {
            asm volatile("cp.async.wait_group 0;");
        }
        __syncthreads();

        const bf16* Ah = (const bf16*)(smbuf + buf * SM_STAGE);
        const bf16* Al = (const bf16*)(smbuf + buf * SM_STAGE + SM_AL);
        const bf16* Bh = (const bf16*)(smbuf + buf * SM_STAGE + SM_BH);
        const bf16* Bl = (const bf16*)(smbuf + buf * SM_STAGE + SM_BL);

        uint32_t ah[4][4], al[4][4];
        #pragma unroll
        for (int mi = 0; mi < 4; mi++) {
            int r = wm + mi * 16 + rl;
            ah[mi][0] = *(const uint32_t*)(Ah + r * 24 + kq * 2);
            ah[mi][1] = *(const uint32_t*)(Ah + (r + 8) * 24 + kq * 2);
            ah[mi][2] = *(const uint32_t*)(Ah + r * 24 + kq * 2 + 8);
            ah[mi][3] = *(const uint32_t*)(Ah + (r + 8) * 24 + kq * 2 + 8);
            al[mi][0] = *(const uint32_t*)(Al + r * 24 + kq * 2);
            al[mi][1] = *(const uint32_t*)(Al + (r + 8) * 24 + kq * 2);
            al[mi][2] = *(const uint32_t*)(Al + r * 24 + kq * 2 + 8);
            al[mi][3] = *(const uint32_t*)(Al + (r + 8) * 24 + kq * 2 + 8);
        }

        #pragma unroll
        for (int nh = 0; nh < 2; nh++) {
            uint32_t bh[4][2], bl[4][2];
            #pragma unroll
            for (int nj = 0; nj < 4; nj++) {
                int n = wn + nh * 32 + nj * 8 + rl;
                bh[nj][0] = *(const uint32_t*)(Bh + n * 24 + kq * 2);
                bh[nj][1] = *(const uint32_t*)(Bh + n * 24 + kq * 2 + 8);
                bl[nj][0] = *(const uint32_t*)(Bl + n * 24 + kq * 2);
                bl[nj][1] = *(const uint32_t*)(Bl + n * 24 + kq * 2 + 8);
            }
            #pragma unroll
            for (int mi = 0; mi < 4; mi++)
                #pragma unroll
                for (int nj = 0; nj < 4; nj++) {
                    float* c = acc[mi][nh * 4 + nj];
                    mma16816(c, ah[mi], bh[nj]);
                    mma16816(c, ah[mi], bl[nj]);
                    mma16816(c, al[mi], bh[nj]);
                }
        }
        __syncthreads();
    }

    // ---- epilogue ----
    #pragma unroll
    for (int nn = 0; nn < 8; nn++) {
        int col = wn + nn * 8 + kq * 2;
        float2 bb = make_float2(0.f, 0.f);
        if (ADD_BIAS) bb = *(const float2*)(bias + col);
        #pragma unroll
        for (int mi = 0; mi < 4; mi++) {
            int r = rowBase + wm + mi * 16 + rl;
            if (OUT_SPLIT) {
                if (r < M) {
                    float vx = acc[mi][nn][0], vy = acc[mi][nn][1];
                    float hx = __bfloat162float(__float2bfloat16(vx));
                    float hy = __bfloat162float(__float2bfloat16(vy));
                    *(uint32_t*)(Ohi + (size_t)r * HID + col) = pack2(vx, vy);
                    *(uint32_t*)(Olo + (size_t)r * HID + col) = pack2(vx - hx, vy - hy);
                }
                if (r + 8 < M) {
                    float vx = acc[mi][nn][2], vy = acc[mi][nn][3];
                    float hx = __bfloat162float(__float2bfloat16(vx));
                    float hy = __bfloat162float(__float2bfloat16(vy));
                    *(uint32_t*)(Ohi + (size_t)(r + 8) * HID + col) = pack2(vx, vy);
                    *(uint32_t*)(Olo + (size_t)(r + 8) * HID + col) = pack2(vx - hx, vy - hy);
                }
            } else {
                if (r < M) {
                    float2 v = make_float2(acc[mi][nn][0] + bb.x,
                                           acc[mi][nn][1] + bb.y);
                    *(float2*)(C + (size_t)r * HID + col) = v;
                }
                if (r + 8 < M) {
                    float2 v = make_float2(acc[mi][nn][2] + bb.x,
                                           acc[mi][nn][3] + bb.y);
                    *(float2*)(C + (size_t)(r + 8) * HID + col) = v;
                }
            }
        }
    }

    if (STATS) {
        #pragma unroll
        for (int nn = 0; nn < 8; nn++) {
            float s0 = 0.f, q0 = 0.f, s1 = 0.f, q1 = 0.f;
            #pragma unroll
            for (int mi = 0; mi < 4; mi++) {
                int r = rowBase + wm + mi * 16 + rl;
                if (r < M) {
                    float v0 = acc[mi][nn][0], v1 = acc[mi][nn][1];
                    s0 += v0; q0 += v0 * v0; s1 += v1; q1 += v1 * v1;
                }
                if (r + 8 < M) {
                    float v0 = acc[mi][nn][2], v1 = acc[mi][nn][3];
                    s0 += v0; q0 += v0 * v0; s1 += v1; q1 += v1 * v1;
                }
            }
            #pragma unroll
            for (int o = 16; o >= 4; o >>= 1) {
                s0 += __shfl_down_sync(~0u, s0, o);
                q0 += __shfl_down_sync(~0u, q0, o);
                s1 += __shfl_down_sync(~0u, s1, o);
                q1 += __shfl_down_sync(~0u, q1, o);
            }
            if (l < 4) {
                int col = wn + nn * 8 + kq * 2;
                atomicAdd(&s_sum[col], s0);     atomicAdd(&s_sq[col], q0);
                atomicAdd(&s_sum[col + 1], s1); atomicAdd(&s_sq[col + 1], q1);
            }
        }
        __syncthreads();
        atomicAdd(&g_sum[tid],   (double)s_sum[tid]);
        atomicAdd(&g_sumsq[tid], (double)s_sq[tid]);
    }
}

// ---------------- gather kernels ----------------
// gather1: width 128, 4x edge unroll (1 float4 accumulator -> low reg cost).
__global__ void __launch_bounds__(256)
gather1_kernel(const float* __restrict__ x, bf16* __restrict__ hi,
               bf16* __restrict__ lo, int M)
{
    const int lane = threadIdx.x & 31;
    int gwarp = (blockIdx.x * blockDim.x + threadIdx.x) >> 5;
    int nwarp = (gridDim.x * blockDim.x) >> 5;

    for (int n = gwarp; n < M; n += nwarp) {
        const float dn = g_dis[n];
        float4 a = __ldg((const float4*)(x + (size_t)n * NFEAT) + lane);
        a.x *= dn; a.y *= dn; a.z *= dn; a.w *= dn;
        const int roff = g_rowoff[n];
        const int dc = g_deg[n];
        int j = 0;
        for (; j + 3 < dc; j += 4) {
            int s0 = __ldg(g_csr + roff + j);
            int s1 = __ldg(g_csr + roff + j + 1);
            int s2 = __ldg(g_csr + roff + j + 2);
            int s3 = __ldg(g_csr + roff + j + 3);
            float d0 = g_dis[s0], d1 = g_dis[s1];
            float d2 = g_dis[s2], d3 = g_dis[s3];
            float4 b = __ldg((const float4*)(x + (size_t)s0 * NFEAT) + lane);
            float4 c = __ldg((const float4*)(x + (size_t)s1 * NFEAT) + lane);
            float4 e = __ldg((const float4*)(x + (size_t)s2 * NFEAT) + lane);
            float4 f = __ldg((const float4*)(x + (size_t)s3 * NFEAT) + lane);
            a.x += b.x * d0 + c.x * d1 + e.x * d2 + f.x * d3;
            a.y += b.y * d0 + c.y * d1 + e.y * d2 + f.y * d3;
            a.z += b.z * d0 + c.z * d1 + e.z * d2 + f.z * d3;
            a.w += b.w * d0 + c.w * d1 + e.w * d2 + f.w * d3;
        }
        for (; j < dc; j++) {
            int s0 = __ldg(g_csr + roff + j);
            float d0 = g_dis[s0];
            float4 b = __ldg((const float4*)(x + (size_t)s0 * NFEAT) + lane);
            a.x += b.x * d0; a.y += b.y * d0; a.z += b.z * d0; a.w += b.w * d0;
        }
        a.x *= dn; a.y *= dn; a.z *= dn; a.w *= dn;
        uint2 H, L;
        split4(a, H, L);
        *((uint2*)(hi + (size_t)n * NFEAT) + lane) = H;
        *((uint2*)(lo + (size_t)n * NFEAT) + lane) = L;
    }
}

// gather2: TWO WARPS PER NODE (column halves), 4x edge unroll.
// Each warp owns 128 of 256 cols -> 1 float4 accumulator, 4 float4 temps.
// BN1 affine (g_bns/g_bnt) commuted past aggregation:
//   out = u*s + r*t, u = dn*(dn*h_i + sum dj*h_j), r = dn*(dn + sum dj)
__global__ void __launch_bounds__(256)
gather2_kernel(const float* __restrict__ h, bf16* __restrict__ hi,
               bf16* __restrict__ lo, int M)
{
    const int lane = threadIdx.x & 31;
    int gunit = (blockIdx.x * blockDim.x + threadIdx.x) >> 5;
    int nunit = (gridDim.x * blockDim.x) >> 5;

    const int M2 = M * 2;
    for (int u = gunit; u < M2; u += nunit) {
        const int n = u >> 1;
        const int half = u & 1;
        const int fo = half * 32 + lane;          // float4 offset within row
        const int co = half * 128 + lane * 4;     // float column offset

        const float4 sv = *(const float4*)(g_bns + co);
        const float4 tv = *(const float4*)(g_bnt + co);

        const float dn = g_dis[n];
        float4 a = __ldg((const float4*)(h + (size_t)n * HID) + fo);
        a.x *= dn; a.y *= dn; a.z *= dn; a.w *= dn;
        float w = dn;

        const int roff = g_rowoff[n];
        const int dc = g_deg[n];
        int j = 0;
        for (; j + 3 < dc; j += 4) {
            int e0 = __ldg(g_csr + roff + j);
            int e1 = __ldg(g_csr + roff + j + 1);
            int e2 = __ldg(g_csr + roff + j + 2);
            int e3 = __ldg(g_csr + roff + j + 3);
            float d0 = g_dis[e0], d1 = g_dis[e1];
            float d2 = g_dis[e2], d3 = g_dis[e3];
            float4 b = __ldg((const float4*)(h + (size_t)e0 * HID) + fo);
            float4 c = __ldg((const float4*)(h + (size_t)e1 * HID) + fo);
            float4 e = __ldg((const float4*)(h + (size_t)e2 * HID) + fo);
            float4 f = __ldg((const float4*)(h + (size_t)e3 * HID) + fo);
            a.x += b.x * d0 + c.x * d1 + e.x * d2 + f.x * d3;
            a.y += b.y * d0 + c.y * d1 + e.y * d2 + f.y * d3;
            a.z += b.z * d0 + c.z * d1 + e.z * d2 + f.z * d3;
            a.w += b.w * d0 + c.w * d1 + e.w * d2 + f.w * d3;
            w += d0 + d1 + d2 + d3;
        }
        for (; j < dc; j++) {
            int e0 = __ldg(g_csr + roff + j);
            float d0 = g_dis[e0];
            float4 b = __ldg((const float4*)(h + (size_t)e0 * HID) + fo);
            a.x += b.x * d0; a.y += b.y * d0; a.z += b.z * d0; a.w += b.w * d0;
            w += d0;
        }

        const float r = dn * w;
        float4 v;
        v.x = fmaf(dn * a.x, sv.x, r * tv.x);
        v.y = fmaf(dn * a.y, sv.y, r * tv.y);
        v.z = fmaf(dn * a.z, sv.z, r * tv.z);
        v.w = fmaf(dn * a.w, sv.w, r * tv.w);

        uint2 H, L;
        split4(v, H, L);
        *((uint2*)(hi + (size_t)n * HID + co)) = H;
        *((uint2*)(lo + (size_t)n * HID + co)) = L;
    }
}

__global__ void bn_finalize(const float* __restrict__ gamma,
                            const float* __restrict__ beta, int M)
{
    int c = threadIdx.x;
    double m   = g_sum[c] / (double)M;
    double var = g_sumsq[c] / (double)M - m * m;
    float sc = gamma[c] * rsqrtf((float)var + BN_EPS);
    g_bns[c] = sc;
    g_bnt[c] = beta[c] - (float)m * sc;
    g_sum[c] = 0.0; g_sumsq[c] = 0.0;   // ready for next layer's stats
}

// ---------------- launch ----------------
extern "C" void kernel_launch(void* const* d_in, const int* in_sizes, int n_in,
                              void* d_out, int out_size)
{
    const float* x   = (const float*)d_in[0];
    const void*  ei  = d_in[1];
    const float* W1  = (const float*)d_in[2];
    const float* g1  = (const float*)d_in[4];
    const float* be1 = (const float*)d_in[5];
    const float* W2  = (const float*)d_in[6];
    const float* g2  = (const float*)d_in[8];
    const float* be2 = (const float*)d_in[9];
    const float* Wfc = (const float*)d_in[10];
    const float* bfc = (const float*)d_in[11];
    float* out = (float*)d_out;

    const int M = in_sizes[0] / NFEAT;   // 50000
    const int E = in_sizes[1] / 2;       // 800000

    void *p_h, *p_ahi, *p_alo, *p_w1h, *p_w1l, *p_w2h, *p_w2l, *p_wfh, *p_wfl, *p_b2;
    cudaGetSymbolAddress(&p_h, g_h);
    cudaGetSymbolAddress(&p_ahi, g_ahi);
    cudaGetSymbolAddress(&p_alo, g_alo);
    cudaGetSymbolAddress(&p_w1h, g_w1h);
    cudaGetSymbolAddress(&p_w1l, g_w1l);
    cudaGetSymbolAddress(&p_w2h, g_w2h);
    cudaGetSymbolAddress(&p_w2l, g_w2l);
    cudaGetSymbolAddress(&p_wfh, g_wfh);
    cudaGetSymbolAddress(&p_wfl, g_wfl);
    cudaGetSymbolAddress(&p_b2, g_bias2);
    float* h = (float*)p_h;
    bf16 *ahi = (bf16*)p_ahi, *alo = (bf16*)p_alo;

    const int TB = 256;
    const int NB = (M + 255) / 256;
    const int gemmGrid = (M + 127) / 128;
    const int gatherBlocks = 592;
    const int SMEM = 2 * SM_STAGE;
    const int Escan = (E < 8192) ? E : 8192;
    const int WSPLIT_N = NFEAT * HID + HID * HID;

    cudaFuncSetAttribute(gemm_mma<NFEAT, false, true, false>,
                         cudaFuncAttributeMaxDynamicSharedMemorySize, SMEM);
    cudaFuncSetAttribute(gemm_mma<HID, false, true, true>,
                         cudaFuncAttributeMaxDynamicSharedMemorySize, SMEM);
    cudaFuncSetAttribute(gemm_mma<HID, true, false, false>,
                         cudaFuncAttributeMaxDynamicSharedMemorySize, SMEM);

    // ---- prep ----
    init_kernel<<<NB, TB>>>((const unsigned long long*)ei, Escan, M, M);
    convert_kernel<<<(E + TB - 1) / TB, TB>>>(ei, E);
    partsum_kernel<<<NB, 256>>>(M);
    scanfinal_kernel<<<NB, 256>>>(M, NB);
    fill_kernel<<<(E + TB - 1) / TB, TB>>>(E);
    wsplit_all<<<(WSPLIT_N + TB - 1) / TB, TB>>>(W1, W2);

    // ---- layer 1: a = split(A_hat x) ; h1 = a @ W1 (stats fused) ----
    gather1_kernel<<<gatherBlocks, TB>>>(x, ahi, alo, M);
    gemm_mma<NFEAT, false, true, false><<<gemmGrid, TB, SMEM>>>(
        ahi, alo, (bf16*)p_w1h, (bf16*)p_w1l, h, nullptr, nullptr, M, nullptr);
    bn_finalize<<<1, HID>>>(g1, be1, M);

    // ---- layer 2: a = split(A_hat bn1(h1)) ; split(h2) = a @ W2 direct ----
    gather2_kernel<<<gatherBlocks, TB>>>(h, ahi, alo, M);
    gemm_mma<HID, false, true, true><<<gemmGrid, TB, SMEM>>>(
        ahi, alo, (bf16*)p_w2h, (bf16*)p_w2l, nullptr, ahi, alo, M, nullptr);
    bn_finalize<<<1, HID>>>(g2, be2, M);

    // ---- FC: fold bn2 into Wfc/bias, then out = split(h2) @ Wfc' + bias' ----
    wfc_fold_kernel<<<HID, HID>>>(Wfc, bfc);
    gemm_mma<HID, true, false, false><<<gemmGrid, TB, SMEM>>>(
        ahi, alo, (bf16*)p_wfh, (bf16*)p_wfl, out, nullptr, nullptr, M,
        (float*)p_b2);
}

// round 17
// speedup vs baseline: 1.0655x; 1.0655x over previous
#include <cuda_runtime.h>
#include <cuda_bf16.h>
#include <cstdint>

#define N_NODES_MAX 50000
#define N_EDGES_MAX 800000
#define NFEAT 128
#define HID 256
#define BN_EPS 1e-5f

typedef __nv_bfloat16 bf16;

// ---------------- scratch (static __device__, no allocation) ----------------
__device__ float  g_h  [(size_t)N_NODES_MAX * HID];
__device__ bf16   g_ahi[(size_t)N_NODES_MAX * HID];
__device__ bf16   g_alo[(size_t)N_NODES_MAX * HID];
__device__ bf16   g_w1h[HID * NFEAT], g_w1l[HID * NFEAT];     // [N][K] transposed
__device__ bf16   g_w2h[HID * HID],   g_w2l[HID * HID];
__device__ bf16   g_wfh[HID * HID],   g_wfl[HID * HID];
__device__ float  g_dis[N_NODES_MAX];
__device__ int    g_deg[N_NODES_MAX];
__device__ int    g_rowoff[N_NODES_MAX];
__device__ int    g_cursor[N_NODES_MAX];
__device__ int    g_src[N_EDGES_MAX];
__device__ int    g_dst[N_EDGES_MAX];
__device__ int    g_csr[N_EDGES_MAX];
__device__ int    g_part[256];
__device__ int    g_is32;        // statically 0; set-only (monotone)
__device__ double g_sum[HID];
__device__ double g_sumsq[HID];
__device__ float  g_bns[HID];
__device__ float  g_bnt[HID];
__device__ float  g_bias2[HID];  // folded FC bias

// ---------------- prep: init + dtype probe fused ----------------
__global__ void init_kernel(const unsigned long long* __restrict__ p,
                            int Escan, int n, int M) {
    int i = blockIdx.x * blockDim.x + threadIdx.x;
    if (i < n) g_deg[i] = 0;
    if (i < HID) {
        g_sum[i] = 0.0; g_sumsq[i] = 0.0;
        g_bias2[i] = 0.f;
    }
    bool bad = (i < Escan) && (p[i] >= (unsigned long long)M);
    unsigned b = __ballot_sync(~0u, bad);
    if (b && (threadIdx.x & 31) == 0) g_is32 = 1;
}

__global__ void convert_kernel(const void* __restrict__ ei, int E) {
    int e = blockIdx.x * blockDim.x + threadIdx.x;
    if (e >= E) return;
    int s, d;
    if (g_is32) {
        const int* p = (const int*)ei;
        s = p[e]; d = p[E + e];
    } else {
        const long long* p = (const long long*)ei;
        s = (int)p[e]; d = (int)p[(size_t)E + e];
    }
    g_src[e] = s;
    g_dst[e] = d;
    atomicAdd(&g_deg[d], 1);
}

__global__ void __launch_bounds__(256)
partsum_kernel(int M) {
    __shared__ int sh[8];
    const int tid = threadIdx.x;
    int i = blockIdx.x * 256 + tid;
    int v = (i < M) ? g_deg[i] : 0;
    #pragma unroll
    for (int o = 16; o > 0; o >>= 1) v += __shfl_down_sync(~0u, v, o);
    if ((tid & 31) == 0) sh[tid >> 5] = v;
    __syncthreads();
    if (tid < 8) {
        int w = sh[tid];
        #pragma unroll
        for (int o = 4; o > 0; o >>= 1) w += __shfl_down_sync(0xffu, w, o);
        if (tid == 0) g_part[blockIdx.x] = w;
    }
}

// scanfinal: block offset computed inline (masked reduction over g_part),
// then intra-block shuffle scan. Replaces the separate scanpart kernel.
__global__ void __launch_bounds__(256)
scanfinal_kernel(int M, int NB) {
    __shared__ int sh[8];
    __shared__ int shOff;
    const int tid = threadIdx.x;

    int pv = (tid < NB && tid < blockIdx.x) ? g_part[tid] : 0;
    #pragma unroll
    for (int o = 16; o > 0; o >>= 1) pv += __shfl_down_sync(~0u, pv, o);
    if ((tid & 31) == 0) sh[tid >> 5] = pv;
    __syncthreads();
    if (tid < 8) {
        int w = sh[tid];
        #pragma unroll
        for (int o = 4; o > 0; o >>= 1) w += __shfl_down_sync(0xffu, w, o);
        if (tid == 0) shOff = w;
    }
    __syncthreads();
    const int blockOff = shOff;
    __syncthreads();

    int i = blockIdx.x * 256 + tid;
    int d = (i < M) ? g_deg[i] : 0;
    int v = d;
    #pragma unroll
    for (int o = 1; o < 32; o <<= 1) {
        int u = __shfl_up_sync(~0u, v, o);
        if ((tid & 31) >= o) v += u;
    }
    if ((tid & 31) == 31) sh[tid >> 5] = v;
    __syncthreads();
    if (tid < 8) {
        int w = sh[tid];
        #pragma unroll
        for (int o = 1; o < 8; o <<= 1) {
            int u = __shfl_up_sync(0xffu, w, o);
            if (tid >= o) w += u;
        }
        sh[tid] = w;
    }
    __syncthreads();
    int warpBase = (tid >= 32) ? sh[(tid >> 5) - 1] : 0;
    int excl = blockOff + warpBase + v - d;
    if (i < M) {
        g_rowoff[i] = excl;
        g_cursor[i] = excl;
        g_dis[i] = rsqrtf((float)(d + 1));
    }
}

__global__ void fill_kernel(int E) {
    int e = blockIdx.x * blockDim.x + threadIdx.x;
    if (e >= E) return;
    int d = g_dst[e];
    int pos = atomicAdd(&g_cursor[d], 1);
    g_csr[pos] = g_src[e];
}

// ---------------- W1 + W2 splits (transposed) ----------------
__global__ void wsplit_all(const float* __restrict__ W1,
                           const float* __restrict__ W2) {
    int idx = blockIdx.x * blockDim.x + threadIdx.x;
    const float* W; bf16 *hip, *lop; int K; int off;
    const int S1 = NFEAT * HID, S2 = S1 + HID * HID;
    if (idx < S1)      { W = W1; hip = g_w1h; lop = g_w1l; K = NFEAT; off = idx; }
    else if (idx < S2) { W = W2; hip = g_w2h; lop = g_w2l; K = HID;   off = idx - S1; }
    else return;
    int k = off >> 8;
    int n = off & 255;
    float v = W[off];
    bf16 h = __float2bfloat16(v);
    bf16 l = __float2bfloat16(v - __bfloat162float(h));
    hip[(size_t)n * K + k] = h;
    lop[(size_t)n * K + k] = l;
}

// ---------------- Wfc fold (reads precomputed g_bns/g_bnt from bn2) -------
__global__ void __launch_bounds__(HID)
wfc_fold_kernel(const float* __restrict__ Wfc,
                const float* __restrict__ bfc) {
    int k = blockIdx.x;
    int n = threadIdx.x;
    float sc = g_bns[k];
    float tt = g_bnt[k];
    float w = Wfc[(size_t)k * HID + n];
    float v = sc * w;
    bf16 h = __float2bfloat16(v);
    bf16 l = __float2bfloat16(v - __bfloat162float(h));
    g_wfh[(size_t)n * HID + k] = h;
    g_wfl[(size_t)n * HID + k] = l;
    float contrib = tt * w;
    if (k == 0) contrib += bfc[n];   // add base bias exactly once
    atomicAdd(&g_bias2[n], contrib);
}

// ---------------- split helpers ----------------
__device__ __forceinline__ uint32_t pack2(float a, float b) {
    __nv_bfloat162 t = __floats2bfloat162_rn(a, b);
    return *(uint32_t*)&t;
}

__device__ __forceinline__ void split4(const float4 v, uint2& H, uint2& L) {
    float hx = __bfloat162float(__float2bfloat16(v.x));
    float hy = __bfloat162float(__float2bfloat16(v.y));
    float hz = __bfloat162float(__float2bfloat16(v.z));
    float hw = __bfloat162float(__float2bfloat16(v.w));
    H.x = pack2(v.x, v.y); H.y = pack2(v.z, v.w);
    L.x = pack2(v.x - hx, v.y - hy); L.y = pack2(v.z - hz, v.w - hw);
}

// ---------------- tensor-core GEMM ----------------
__device__ __forceinline__ void mma16816(float* c, const uint32_t* a,
                                         const uint32_t* b) {
    asm volatile(
        "mma.sync.aligned.m16n8k16.row.col.f32.bf16.bf16.f32 "
        "{%0,%1,%2,%3}, {%4,%5,%6,%7}, {%8,%9}, {%0,%1,%2,%3};"
        : "+f"(c[0]), "+f"(c[1]), "+f"(c[2]), "+f"(c[3])
        : "r"(a[0]), "r"(a[1]), "r"(a[2]), "r"(a[3]), "r"(b[0]), "r"(b[1]));
}

__device__ __forceinline__ void cpa16(void* s, const void* g) {
    uint32_t sa = (uint32_t)__cvta_generic_to_shared(s);
    asm volatile("cp.async.cg.shared.global [%0], [%1], 16;" :: "r"(sa), "l"(g));
}

#define SM_STAGE 36864
#define SM_AL    6144
#define SM_BH    12288
#define SM_BL    24576

// OUT_SPLIT: write split(C) bf16 hi/lo (to Ohi/Olo) instead of fp32 C.
// Aliasing-safe: each block reads/writes only its own 128-row slice.
template<int K, bool ADD_BIAS, bool STATS, bool OUT_SPLIT>
__global__ void __launch_bounds__(256)
gemm_mma(const bf16* __restrict__ Ahi, const bf16* __restrict__ Alo,
         const bf16* __restrict__ Bhi, const bf16* __restrict__ Blo,
         float* __restrict__ C, bf16* __restrict__ Ohi, bf16* __restrict__ Olo,
         int M, const float* __restrict__ bias)
{
    extern __shared__ char smbuf[];
    __shared__ float s_sum[HID], s_sq[HID];
    constexpr int NK = K / 16;
    const int tid = threadIdx.x;
    const int l   = tid & 31;
    const int wid = tid >> 5;
    const int wm  = (wid & 1) * 64;
    const int wn  = (wid >> 1) * 64;
    const int rowBase = blockIdx.x * 128;

    const int arow  = tid >> 1;
    const int ahalf = tid & 1;
    const int gar   = min(rowBase + arow, M - 1);
    const size_t aoff = (size_t)gar * K + ahalf * 8;
    const int asm_off = arow * 48 + ahalf * 16;

    if (STATS) { s_sum[tid] = 0.f; s_sq[tid] = 0.f; }

    float acc[4][8][4] = {};

    auto issue = [&](int kt, int buf) {
        char* st = smbuf + buf * SM_STAGE;
        int ko = kt * 16;
        cpa16(st + asm_off,         Ahi + aoff + ko);
        cpa16(st + SM_AL + asm_off, Alo + aoff + ko);
        #pragma unroll
        for (int q = 0; q < 2; q++) {
            int slot = tid + q * 256;
            int n = slot >> 1, hh = slot & 1;
            size_t boff = (size_t)n * K + ko + hh * 8;
            int so = n * 48 + hh * 16;
            cpa16(st + SM_BH + so, Bhi + boff);
            cpa16(st + SM_BL + so, Blo + boff);
        }
    };

    issue(0, 0);
    asm volatile("cp.async.commit_group;");

    const int kq = l & 3;
    const int rl = l >> 2;

    for (int kt = 0; kt < NK; kt++) {
        const int buf = kt & 1;
        if (kt + 1 < NK) {
            issue(kt + 1, buf ^ 1);
            asm volatile("cp.async.commit_group;");
            asm volatile("cp.async.wait_group 1;");
        } else {
            asm volatile("cp.async.wait_group 0;");
        }
        __syncthreads();

        const bf16* Ah = (const bf16*)(smbuf + buf * SM_STAGE);
        const bf16* Al = (const bf16*)(smbuf + buf * SM_STAGE + SM_AL);
        const bf16* Bh = (const bf16*)(smbuf + buf * SM_STAGE + SM_BH);
        const bf16* Bl = (const bf16*)(smbuf + buf * SM_STAGE + SM_BL);

        uint32_t ah[4][4], al[4][4];
        #pragma unroll
        for (int mi = 0; mi < 4; mi++) {
            int r = wm + mi * 16 + rl;
            ah[mi][0] = *(const uint32_t*)(Ah + r * 24 + kq * 2);
            ah[mi][1] = *(const uint32_t*)(Ah + (r + 8) * 24 + kq * 2);
            ah[mi][2] = *(const uint32_t*)(Ah + r * 24 + kq * 2 + 8);
            ah[mi][3] = *(const uint32_t*)(Ah + (r + 8) * 24 + kq * 2 + 8);
            al[mi][0] = *(const uint32_t*)(Al + r * 24 + kq * 2);
            al[mi][1] = *(const uint32_t*)(Al + (r + 8) * 24 + kq * 2);
            al[mi][2] = *(const uint32_t*)(Al + r * 24 + kq * 2 + 8);
            al[mi][3] = *(const uint32_t*)(Al + (r + 8) * 24 + kq * 2 + 8);
        }

        #pragma unroll
        for (int nh = 0; nh < 2; nh++) {
            uint32_t bh[4][2], bl[4][2];
            #pragma unroll
            for (int nj = 0; nj < 4; nj++) {
                int n = wn + nh * 32 + nj * 8 + rl;
                bh[nj][0] = *(const uint32_t*)(Bh + n * 24 + kq * 2);
                bh[nj][1] = *(const uint32_t*)(Bh + n * 24 + kq * 2 + 8);
                bl[nj][0] = *(const uint32_t*)(Bl + n * 24 + kq * 2);
                bl[nj][1] = *(const uint32_t*)(Bl + n * 24 + kq * 2 + 8);
            }
            #pragma unroll
            for (int mi = 0; mi < 4; mi++)
                #pragma unroll
                for (int nj = 0; nj < 4; nj++) {
                    float* c = acc[mi][nh * 4 + nj];
                    mma16816(c, ah[mi], bh[nj]);
                    mma16816(c, ah[mi], bl[nj]);
                    mma16816(c, al[mi], bh[nj]);
                }
        }
        __syncthreads();
    }

    // ---- epilogue ----
    #pragma unroll
    for (int nn = 0; nn < 8; nn++) {
        int col = wn + nn * 8 + kq * 2;
        float2 bb = make_float2(0.f, 0.f);
        if (ADD_BIAS) bb = *(const float2*)(bias + col);
        #pragma unroll
        for (int mi = 0; mi < 4; mi++) {
            int r = rowBase + wm + mi * 16 + rl;
            if (OUT_SPLIT) {
                if (r < M) {
                    float vx = acc[mi][nn][0], vy = acc[mi][nn][1];
                    float hx = __bfloat162float(__float2bfloat16(vx));
                    float hy = __bfloat162float(__float2bfloat16(vy));
                    *(uint32_t*)(Ohi + (size_t)r * HID + col) = pack2(vx, vy);
                    *(uint32_t*)(Olo + (size_t)r * HID + col) = pack2(vx - hx, vy - hy);
                }
                if (r + 8 < M) {
                    float vx = acc[mi][nn][2], vy = acc[mi][nn][3];
                    float hx = __bfloat162float(__float2bfloat16(vx));
                    float hy = __bfloat162float(__float2bfloat16(vy));
                    *(uint32_t*)(Ohi + (size_t)(r + 8) * HID + col) = pack2(vx, vy);
                    *(uint32_t*)(Olo + (size_t)(r + 8) * HID + col) = pack2(vx - hx, vy - hy);
                }
            } else {
                if (r < M) {
                    float2 v = make_float2(acc[mi][nn][0] + bb.x,
                                           acc[mi][nn][1] + bb.y);
                    *(float2*)(C + (size_t)r * HID + col) = v;
                }
                if (r + 8 < M) {
                    float2 v = make_float2(acc[mi][nn][2] + bb.x,
                                           acc[mi][nn][3] + bb.y);
                    *(float2*)(C + (size_t)(r + 8) * HID + col) = v;
                }
            }
        }
    }

    if (STATS) {
        #pragma unroll
        for (int nn = 0; nn < 8; nn++) {
            float s0 = 0.f, q0 = 0.f, s1 = 0.f, q1 = 0.f;
            #pragma unroll
            for (int mi = 0; mi < 4; mi++) {
                int r = rowBase + wm + mi * 16 + rl;
                if (r < M) {
                    float v0 = acc[mi][nn][0], v1 = acc[mi][nn][1];
                    s0 += v0; q0 += v0 * v0; s1 += v1; q1 += v1 * v1;
                }
                if (r + 8 < M) {
                    float v0 = acc[mi][nn][2], v1 = acc[mi][nn][3];
                    s0 += v0; q0 += v0 * v0; s1 += v1; q1 += v1 * v1;
                }
            }
            #pragma unroll
            for (int o = 16; o >= 4; o >>= 1) {
                s0 += __shfl_down_sync(~0u, s0, o);
                q0 += __shfl_down_sync(~0u, q0, o);
                s1 += __shfl_down_sync(~0u, s1, o);
                q1 += __shfl_down_sync(~0u, q1, o);
            }
            if (l < 4) {
                int col = wn + nn * 8 + kq * 2;
                atomicAdd(&s_sum[col], s0);     atomicAdd(&s_sq[col], q0);
                atomicAdd(&s_sum[col + 1], s1); atomicAdd(&s_sq[col + 1], q1);
            }
        }
        __syncthreads();
        atomicAdd(&g_sum[tid],   (double)s_sum[tid]);
        atomicAdd(&g_sumsq[tid], (double)s_sq[tid]);
    }
}

// ---------------- gather kernels (champion R15 configuration) ----------------
__global__ void __launch_bounds__(256)
gather1_kernel(const float* __restrict__ x, bf16* __restrict__ hi,
               bf16* __restrict__ lo, int M)
{
    const int lane = threadIdx.x & 31;
    int gwarp = (blockIdx.x * blockDim.x + threadIdx.x) >> 5;
    int nwarp = (gridDim.x * blockDim.x) >> 5;

    for (int n = gwarp; n < M; n += nwarp) {
        const float dn = g_dis[n];
        float4 a = __ldg((const float4*)(x + (size_t)n * NFEAT) + lane);
        a.x *= dn; a.y *= dn; a.z *= dn; a.w *= dn;
        const int roff = g_rowoff[n];
        const int dc = g_deg[n];
        int j = 0;
        for (; j + 1 < dc; j += 2) {
            int s0 = __ldg(g_csr + roff + j);
            int s1 = __ldg(g_csr + roff + j + 1);
            float d0 = g_dis[s0], d1 = g_dis[s1];
            float4 b = __ldg((const float4*)(x + (size_t)s0 * NFEAT) + lane);
            float4 c = __ldg((const float4*)(x + (size_t)s1 * NFEAT) + lane);
            a.x += b.x * d0 + c.x * d1; a.y += b.y * d0 + c.y * d1;
            a.z += b.z * d0 + c.z * d1; a.w += b.w * d0 + c.w * d1;
        }
        if (j < dc) {
            int s0 = __ldg(g_csr + roff + j);
            float d0 = g_dis[s0];
            float4 b = __ldg((const float4*)(x + (size_t)s0 * NFEAT) + lane);
            a.x += b.x * d0; a.y += b.y * d0; a.z += b.z * d0; a.w += b.w * d0;
        }
        a.x *= dn; a.y *= dn; a.z *= dn; a.w *= dn;
        uint2 H, L;
        split4(a, H, L);
        *((uint2*)(hi + (size_t)n * NFEAT) + lane) = H;
        *((uint2*)(lo + (size_t)n * NFEAT) + lane) = L;
    }
}

// gather2: raw h input; BN1 affine (precomputed g_bns/g_bnt) commuted past
// aggregation. 1 warp/node, 2x unroll (proven optimum; 4x and warp-split
// both regressed).
__global__ void __launch_bounds__(256)
gather2_kernel(const float* __restrict__ h, bf16* __restrict__ hi,
               bf16* __restrict__ lo, int M)
{
    const int lane = threadIdx.x & 31;
    int gwarp = (blockIdx.x * blockDim.x + threadIdx.x) >> 5;
    int nwarp = (gridDim.x * blockDim.x) >> 5;

    const float4 s0 = *(const float4*)(g_bns + lane * 4);
    const float4 t0 = *(const float4*)(g_bnt + lane * 4);
    const float4 s1 = *(const float4*)(g_bns + 128 + lane * 4);
    const float4 t1 = *(const float4*)(g_bnt + 128 + lane * 4);

    for (int n = gwarp; n < M; n += nwarp) {
        const float dn = g_dis[n];
        const float4* sp = (const float4*)(h + (size_t)n * HID);
        float4 a0 = __ldg(sp + lane);
        float4 a1 = __ldg(sp + lane + 32);
        a0.x *= dn; a0.y *= dn; a0.z *= dn; a0.w *= dn;
        a1.x *= dn; a1.y *= dn; a1.z *= dn; a1.w *= dn;
        float w = dn;

        const int roff = g_rowoff[n];
        const int dc = g_deg[n];
        int j = 0;
        for (; j + 1 < dc; j += 2) {
            int e0 = __ldg(g_csr + roff + j);
            int e1 = __ldg(g_csr + roff + j + 1);
            float d0 = g_dis[e0], d1 = g_dis[e1];
            const float4* p0 = (const float4*)(h + (size_t)e0 * HID);
            const float4* p1 = (const float4*)(h + (size_t)e1 * HID);
            float4 b0 = __ldg(p0 + lane);
            float4 b1 = __ldg(p0 + lane + 32);
            float4 c0 = __ldg(p1 + lane);
            float4 c1 = __ldg(p1 + lane + 32);
            a0.x += b0.x * d0 + c0.x * d1; a0.y += b0.y * d0 + c0.y * d1;
            a0.z += b0.z * d0 + c0.z * d1; a0.w += b0.w * d0 + c0.w * d1;
            a1.x += b1.x * d0 + c1.x * d1; a1.y += b1.y * d0 + c1.y * d1;
            a1.z += b1.z * d0 + c1.z * d1; a1.w += b1.w * d0 + c1.w * d1;
            w += d0 + d1;
        }
        if (j < dc) {
            int e0 = __ldg(g_csr + roff + j);
            float d0 = g_dis[e0];
            const float4* p0 = (const float4*)(h + (size_t)e0 * HID);
            float4 b0 = __ldg(p0 + lane);
            float4 b1 = __ldg(p0 + lane + 32);
            a0.x += b0.x * d0; a0.y += b0.y * d0;
            a0.z += b0.z * d0; a0.w += b0.w * d0;
            a1.x += b1.x * d0; a1.y += b1.y * d0;
            a1.z += b1.z * d0; a1.w += b1.w * d0;
            w += d0;
        }

        const float r = dn * w;
        float4 v0, v1;
        v0.x = fmaf(dn * a0.x, s0.x, r * t0.x);
        v0.y = fmaf(dn * a0.y, s0.y, r * t0.y);
        v0.z = fmaf(dn * a0.z, s0.z, r * t0.z);
        v0.w = fmaf(dn * a0.w, s0.w, r * t0.w);
        v1.x = fmaf(dn * a1.x, s1.x, r * t1.x);
        v1.y = fmaf(dn * a1.y, s1.y, r * t1.y);
        v1.z = fmaf(dn * a1.z, s1.z, r * t1.z);
        v1.w = fmaf(dn * a1.w, s1.w, r * t1.w);

        uint2 H0, L0, H1, L1;
        split4(v0, H0, L0);
        split4(v1, H1, L1);
        *((uint2*)(hi + (size_t)n * HID) + lane) = H0;
        *((uint2*)(hi + (size_t)n * HID) + lane + 32) = H1;
        *((uint2*)(lo + (size_t)n * HID) + lane) = L0;
        *((uint2*)(lo + (size_t)n * HID) + lane + 32) = L1;
    }
}

__global__ void bn_finalize(const float* __restrict__ gamma,
                            const float* __restrict__ beta, int M)
{
    int c = threadIdx.x;
    double m   = g_sum[c] / (double)M;
    double var = g_sumsq[c] / (double)M - m * m;
    float sc = gamma[c] * rsqrtf((float)var + BN_EPS);
    g_bns[c] = sc;
    g_bnt[c] = beta[c] - (float)m * sc;
    g_sum[c] = 0.0; g_sumsq[c] = 0.0;   // ready for next layer's stats
}

// ---------------- launch ----------------
extern "C" void kernel_launch(void* const* d_in, const int* in_sizes, int n_in,
                              void* d_out, int out_size)
{
    const float* x   = (const float*)d_in[0];
    const void*  ei  = d_in[1];
    const float* W1  = (const float*)d_in[2];
    const float* g1  = (const float*)d_in[4];
    const float* be1 = (const float*)d_in[5];
    const float* W2  = (const float*)d_in[6];
    const float* g2  = (const float*)d_in[8];
    const float* be2 = (const float*)d_in[9];
    const float* Wfc = (const float*)d_in[10];
    const float* bfc = (const float*)d_in[11];
    float* out = (float*)d_out;

    const int M = in_sizes[0] / NFEAT;   // 50000
    const int E = in_sizes[1] / 2;       // 800000

    void *p_h, *p_ahi, *p_alo, *p_w1h, *p_w1l, *p_w2h, *p_w2l, *p_wfh, *p_wfl, *p_b2;
    cudaGetSymbolAddress(&p_h, g_h);
    cudaGetSymbolAddress(&p_ahi, g_ahi);
    cudaGetSymbolAddress(&p_alo, g_alo);
    cudaGetSymbolAddress(&p_w1h, g_w1h);
    cudaGetSymbolAddress(&p_w1l, g_w1l);
    cudaGetSymbolAddress(&p_w2h, g_w2h);
    cudaGetSymbolAddress(&p_w2l, g_w2l);
    cudaGetSymbolAddress(&p_wfh, g_wfh);
    cudaGetSymbolAddress(&p_wfl, g_wfl);
    cudaGetSymbolAddress(&p_b2, g_bias2);
    float* h = (float*)p_h;
    bf16 *ahi = (bf16*)p_ahi, *alo = (bf16*)p_alo;

    const int TB = 256;
    const int NB = (M + 255) / 256;
    const int gemmGrid = (M + 127) / 128;
    const int gatherBlocks = 592;
    const int SMEM = 2 * SM_STAGE;
    const int Escan = (E < 8192) ? E : 8192;
    const int WSPLIT_N = NFEAT * HID + HID * HID;

    cudaFuncSetAttribute(gemm_mma<NFEAT, false, true, false>,
                         cudaFuncAttributeMaxDynamicSharedMemorySize, SMEM);
    cudaFuncSetAttribute(gemm_mma<HID, false, true, true>,
                         cudaFuncAttributeMaxDynamicSharedMemorySize, SMEM);
    cudaFuncSetAttribute(gemm_mma<HID, true, false, false>,
                         cudaFuncAttributeMaxDynamicSharedMemorySize, SMEM);

    // ---- prep ----
    init_kernel<<<NB, TB>>>((const unsigned long long*)ei, Escan, M, M);
    convert_kernel<<<(E + TB - 1) / TB, TB>>>(ei, E);
    partsum_kernel<<<NB, 256>>>(M);
    scanfinal_kernel<<<NB, 256>>>(M, NB);
    fill_kernel<<<(E + TB - 1) / TB, TB>>>(E);
    wsplit_all<<<(WSPLIT_N + TB - 1) / TB, TB>>>(W1, W2);

    // ---- layer 1: a = split(A_hat x) ; h1 = a @ W1 (stats fused) ----
    gather1_kernel<<<gatherBlocks, TB>>>(x, ahi, alo, M);
    gemm_mma<NFEAT, false, true, false><<<gemmGrid, TB, SMEM>>>(
        ahi, alo, (bf16*)p_w1h, (bf16*)p_w1l, h, nullptr, nullptr, M, nullptr);
    bn_finalize<<<1, HID>>>(g1, be1, M);

    // ---- layer 2: a = split(A_hat bn1(h1)) ; split(h2) = a @ W2 direct ----
    gather2_kernel<<<gatherBlocks, TB>>>(h, ahi, alo, M);
    gemm_mma<HID, false, true, true><<<gemmGrid, TB, SMEM>>>(
        ahi, alo, (bf16*)p_w2h, (bf16*)p_w2l, nullptr, ahi, alo, M, nullptr);
    bn_finalize<<<1, HID>>>(g2, be2, M);

    // ---- FC: fold bn2 into Wfc/bias, then out = split(h2) @ Wfc' + bias' ----
    wfc_fold_kernel<<<HID, HID>>>(Wfc, bfc);
    gemm_mma<HID, true, false, false><<<gemmGrid, TB, SMEM>>>(
        ahi, alo, (bf16*)p_wfh, (bf16*)p_wfl, out, nullptr, nullptr, M,
        (float*)p_b2);
}